// round 1
// baseline (speedup 1.0000x reference)
#include <cuda_runtime.h>

#define EPS 1e-5f

constexpr int E_MAX = 1600000;
constexpr int N_MAX = 100000;

// ---------------- scratch (device globals; no allocations allowed) ----------
__device__ float g_h1[(size_t)E_MAX * 64];      // edge lin1 output (pre-BN)
__device__ float g_spre[(size_t)N_MAX * 64];    // scatter-sum of relu(bn(h1))
__device__ float g_o1[(size_t)N_MAX * 64];      // node lin (pre-BN)
__device__ float g_cnt[N_MAX];                  // in-degree
__device__ float g_stats[256];                  // [sum1|sq1|sum3|sq3] x64
__device__ float g_bn[256];                     // [a1|c1|a3|c3] x64
__device__ float g_w23[64 * 64];                // w2 @ w3[3:]
__device__ float g_bb[64];                      // b2 @ w3[3:]
__device__ int   g_is64;                        // edge_index dtype flag

// ---------------- helpers ---------------------------------------------------
__device__ __forceinline__ void red4(float* p, float a, float b, float c, float d) {
    asm volatile("red.global.add.v4.f32 [%0], {%1, %2, %3, %4};"
                 :: "l"(p), "f"(a), "f"(b), "f"(c), "f"(d) : "memory");
}

__device__ __forceinline__ long long load_index(const void* ei, size_t pos, int is64) {
    return is64 ? ((const long long*)ei)[pos] : (long long)((const int*)ei)[pos];
}

// 8x4 register-tiled GEMM inner loop.
// zT: [KK][128] transposed A tile, XOR-swizzled: element (k,e) stored at
//     zT[k*128 + (e ^ ((k&7)<<2))]  (swizzle on 4-float granularity).
// ws: [KK][64] B tile (row-major).
template<int KK>
__device__ __forceinline__ void gemm8x4(const float* zT, const float* ws,
                                        int tx, int ty, float acc[8][4])
{
    #pragma unroll 2
    for (int k = 0; k < KK; ++k) {
        int s = (k & 7) << 2;
        float4 wv = *(const float4*)(ws + (k << 6) + (tx << 2));
        float4 za = *(const float4*)(zT + (k << 7) + ((ty << 3) ^ s));
        float4 zb = *(const float4*)(zT + (k << 7) + (((ty << 3) | 4) ^ s));
        float zr[8] = {za.x, za.y, za.z, za.w, zb.x, zb.y, zb.z, zb.w};
        float wr[4] = {wv.x, wv.y, wv.z, wv.w};
        #pragma unroll
        for (int i = 0; i < 8; ++i)
            #pragma unroll
            for (int j = 0; j < 4; ++j)
                acc[i][j] = fmaf(zr[i], wr[j], acc[i][j]);
    }
}

// ---------------- tiny kernels ----------------------------------------------
__global__ void k_detect(const int* ei32) {
    int is64 = 1;
    #pragma unroll
    for (int i = 0; i < 8; ++i) if (ei32[2 * i + 1] != 0) is64 = 0;
    g_is64 = is64;
}

__global__ void k_prep(const float* __restrict__ w2, const float* __restrict__ w3,
                       const float* __restrict__ b2)
{
    int t = threadIdx.x;
    int i = t >> 2, jc = (t & 3) << 4;
    float acc[16];
    #pragma unroll
    for (int j = 0; j < 16; ++j) acc[j] = 0.f;
    for (int k = 0; k < 64; ++k) {
        float a = w2[i * 64 + k];
        const float* wr = w3 + (3 + k) * 64 + jc;
        #pragma unroll
        for (int j = 0; j < 16; ++j) acc[j] = fmaf(a, wr[j], acc[j]);
    }
    for (int j = 0; j < 16; ++j) g_w23[i * 64 + jc + j] = acc[j];
    if (t < 64) {
        float s = 0.f;
        for (int k = 0; k < 64; ++k) s = fmaf(b2[k], w3[(3 + k) * 64 + t], s);
        g_bb[t] = s;
    }
}

__global__ void k_bnfin(const float* __restrict__ g, const float* __restrict__ be,
                        int so, int bo, float invM)
{
    int j = threadIdx.x;  // 64 threads
    float m = g_stats[so + j] * invM;
    float v = g_stats[so + 64 + j] * invM - m * m;
    float a = g[j] * rsqrtf(v + EPS);
    g_bn[bo + j] = a;
    g_bn[bo + 64 + j] = be[j] - m * a;
}

// ---------------- K1: edge lin1 + BN stats ----------------------------------
// h1[e] = concat(x[row[e]], ea[e]) @ w1 + b1, 128 edges/block
__global__ __launch_bounds__(256, 2)
void k_edge(const float* __restrict__ x, const void* __restrict__ ei,
            const float* __restrict__ ea, const float* __restrict__ w1,
            const float* __restrict__ b1, int E)
{
    extern __shared__ float smem_f[];
    float* zT    = smem_f;              // 67*128
    float* ws    = zT + 67 * 128;       // 67*64
    float* wpart = ws + 67 * 64;        // 8*128
    int t = threadIdx.x;
    int w = t >> 5, lane = t & 31;
    int e0 = blockIdx.x * 128;
    int is64 = g_is64;

    // W tile, permuted: ws row kk <- w1 row (kk<64 ? kk+3 : kk-64)
    {
        const float4* w4p = (const float4*)w1;
        float4* wd = (float4*)ws;
        for (int i = t; i < 67 * 16; i += 256) {
            int kk = i >> 4, v = i & 15;
            int src = (kk < 64) ? (kk + 3) : (kk - 64);
            wd[i] = w4p[src * 16 + v];
        }
    }
    // zT rows 0..63: edge_attr, transposed via coalesced reads + swizzled STS128
    #pragma unroll
    for (int it = 0; it < 8; ++it) {
        int task = w + 8 * it;                 // 64 tasks: 2 k-halves x 32 e-chunks
        int k = ((task & 1) << 5) + lane;
        int ec = task >> 1;
        int e = e0 + 4 * ec;
        float r0 = 0.f, r1 = 0.f, r2 = 0.f, r3 = 0.f;
        if (e + 0 < E) r0 = ea[(size_t)(e + 0) * 64 + k];
        if (e + 1 < E) r1 = ea[(size_t)(e + 1) * 64 + k];
        if (e + 2 < E) r2 = ea[(size_t)(e + 2) * 64 + k];
        if (e + 3 < E) r3 = ea[(size_t)(e + 3) * 64 + k];
        int es = (4 * ec) ^ ((k & 7) << 2);
        *(float4*)(zT + k * 128 + es) = make_float4(r0, r1, r2, r3);
    }
    // zT rows 64..66: gathered x[row[e]]
    if (t < 128) {
        int e = e0 + t;
        float x0 = 0.f, x1 = 0.f, x2 = 0.f;
        if (e < E) {
            long long row = load_index(ei, (size_t)e, is64);
            const float* xp = x + row * 3;
            x0 = xp[0]; x1 = xp[1]; x2 = xp[2];
        }
        zT[64 * 128 + t]       = x0;   // swz(64)=0
        zT[65 * 128 + (t ^ 4)] = x1;   // swz(65)=4
        zT[66 * 128 + (t ^ 8)] = x2;   // swz(66)=8
    }
    __syncthreads();

    int tx = t & 15, ty = t >> 4;
    float acc[8][4];
    #pragma unroll
    for (int i = 0; i < 8; ++i)
        #pragma unroll
        for (int j = 0; j < 4; ++j) acc[i][j] = 0.f;

    gemm8x4<67>(zT, ws, tx, ty, acc);

    // epilogue: bias, store h1, per-feature sum/sumsq
    float bv0 = __ldg(b1 + 4 * tx + 0), bv1 = __ldg(b1 + 4 * tx + 1);
    float bv2 = __ldg(b1 + 4 * tx + 2), bv3 = __ldg(b1 + 4 * tx + 3);
    float cs[4] = {0, 0, 0, 0}, cq[4] = {0, 0, 0, 0};
    #pragma unroll
    for (int i = 0; i < 8; ++i) {
        int e = e0 + (ty << 3) + i;
        if (e < E) {
            float v0 = acc[i][0] + bv0, v1 = acc[i][1] + bv1;
            float v2 = acc[i][2] + bv2, v3 = acc[i][3] + bv3;
            *(float4*)(g_h1 + (size_t)e * 64 + (tx << 2)) = make_float4(v0, v1, v2, v3);
            cs[0] += v0; cs[1] += v1; cs[2] += v2; cs[3] += v3;
            cq[0] += v0 * v0; cq[1] += v1 * v1; cq[2] += v2 * v2; cq[3] += v3 * v3;
        }
    }
    #pragma unroll
    for (int j = 0; j < 4; ++j) {
        cs[j] += __shfl_xor_sync(0xffffffffu, cs[j], 16);
        cq[j] += __shfl_xor_sync(0xffffffffu, cq[j], 16);
    }
    if (lane < 16) {
        *(float4*)(wpart + w * 128 + (lane << 2))      = make_float4(cs[0], cs[1], cs[2], cs[3]);
        *(float4*)(wpart + w * 128 + 64 + (lane << 2)) = make_float4(cq[0], cq[1], cq[2], cq[3]);
    }
    __syncthreads();
    if (t < 128) {
        float s = 0.f;
        #pragma unroll
        for (int ww = 0; ww < 8; ++ww) s += wpart[ww * 128 + t];
        atomicAdd(&g_stats[t], s);   // [0..63]=sum, [64..127]=sumsq
    }
}

// ---------------- K3: normalize+relu+scatter (vector atomics) ---------------
__global__ __launch_bounds__(256)
void k_scatter(const void* __restrict__ ei, int E)
{
    __shared__ float a1s[64], c1s[64];
    __shared__ int cols[32];
    int t = threadIdx.x;
    int e0 = blockIdx.x * 32;
    int is64 = g_is64;
    if (t < 64) { a1s[t] = g_bn[t]; c1s[t] = g_bn[64 + t]; }
    else if (t < 96) {
        int e = e0 + t - 64;
        int c = 0;
        if (e < E) c = (int)load_index(ei, (size_t)E + e, is64);
        cols[t - 64] = c;
    }
    __syncthreads();
    int el = t >> 3, p = t & 7;
    int e = e0 + el;
    if (e >= E) return;
    const float4* h4 = (const float4*)(g_h1 + (size_t)e * 64);
    float4 v0 = h4[2 * p], v1 = h4[2 * p + 1];
    int j0 = p * 8;
    float r0 = fmaxf(fmaf(v0.x, a1s[j0 + 0], c1s[j0 + 0]), 0.f);
    float r1 = fmaxf(fmaf(v0.y, a1s[j0 + 1], c1s[j0 + 1]), 0.f);
    float r2 = fmaxf(fmaf(v0.z, a1s[j0 + 2], c1s[j0 + 2]), 0.f);
    float r3 = fmaxf(fmaf(v0.w, a1s[j0 + 3], c1s[j0 + 3]), 0.f);
    float r4 = fmaxf(fmaf(v1.x, a1s[j0 + 4], c1s[j0 + 4]), 0.f);
    float r5 = fmaxf(fmaf(v1.y, a1s[j0 + 5], c1s[j0 + 5]), 0.f);
    float r6 = fmaxf(fmaf(v1.z, a1s[j0 + 6], c1s[j0 + 6]), 0.f);
    float r7 = fmaxf(fmaf(v1.w, a1s[j0 + 7], c1s[j0 + 7]), 0.f);
    float* dst = g_spre + (size_t)cols[el] * 64 + j0;
    red4(dst,     r0, r1, r2, r3);
    red4(dst + 4, r4, r5, r6, r7);
    if (p == 0) atomicAdd(&g_cnt[cols[el]], 1.0f);
}

// ---------------- K4: node lin (fused w2@w3b) + BN stats --------------------
__global__ __launch_bounds__(256, 2)
void k_node1(const float* __restrict__ x, const float* __restrict__ w3,
             const float* __restrict__ b3, int N)
{
    extern __shared__ float smem_f[];
    float* zT    = smem_f;               // 67*128
    float* ws    = zT + 67 * 128;        // 67*64
    float* wpart = ws + 67 * 64;         // 8*128
    float* rcpS  = wpart + 1024;         // 128
    float* indS  = rcpS + 128;           // 128
    int t = threadIdx.x;
    int w = t >> 5, lane = t & 31;
    int n0 = blockIdx.x * 128;

    {   // W: rows 0..63 = w23, rows 64..66 = w3[0..2]
        float4* wd = (float4*)ws;
        const float4* a4 = (const float4*)g_w23;
        for (int i = t; i < 64 * 16; i += 256) wd[i] = a4[i];
        const float4* b4p = (const float4*)w3;
        if (t < 48) wd[64 * 16 + t] = b4p[t];
    }
    if (t < 128) {
        int n = n0 + t;
        float c = (n < N) ? g_cnt[n] : 0.f;
        rcpS[t] = 1.f / fmaxf(c, 1.f);
        indS[t] = (c > 0.f) ? 1.f : 0.f;
        float x0 = 0.f, x1 = 0.f, x2 = 0.f;
        if (n < N) { x0 = x[n * 3]; x1 = x[n * 3 + 1]; x2 = x[n * 3 + 2]; }
        zT[64 * 128 + t]       = x0;
        zT[65 * 128 + (t ^ 4)] = x1;
        zT[66 * 128 + (t ^ 8)] = x2;
    }
    __syncthreads();
    #pragma unroll
    for (int it = 0; it < 8; ++it) {
        int task = w + 8 * it;
        int k = ((task & 1) << 5) + lane;
        int ec = task >> 1;
        int n = n0 + 4 * ec;
        float r0 = 0.f, r1 = 0.f, r2 = 0.f, r3 = 0.f;
        if (n + 0 < N) r0 = g_spre[(size_t)(n + 0) * 64 + k] * rcpS[4 * ec + 0];
        if (n + 1 < N) r1 = g_spre[(size_t)(n + 1) * 64 + k] * rcpS[4 * ec + 1];
        if (n + 2 < N) r2 = g_spre[(size_t)(n + 2) * 64 + k] * rcpS[4 * ec + 2];
        if (n + 3 < N) r3 = g_spre[(size_t)(n + 3) * 64 + k] * rcpS[4 * ec + 3];
        int es = (4 * ec) ^ ((k & 7) << 2);
        *(float4*)(zT + k * 128 + es) = make_float4(r0, r1, r2, r3);
    }
    __syncthreads();

    int tx = t & 15, ty = t >> 4;
    float acc[8][4];
    #pragma unroll
    for (int i = 0; i < 8; ++i)
        #pragma unroll
        for (int j = 0; j < 4; ++j) acc[i][j] = 0.f;

    gemm8x4<67>(zT, ws, tx, ty, acc);

    float b3v[4], bbv[4];
    #pragma unroll
    for (int j = 0; j < 4; ++j) { b3v[j] = __ldg(b3 + 4 * tx + j); bbv[j] = g_bb[4 * tx + j]; }
    float cs[4] = {0, 0, 0, 0}, cq[4] = {0, 0, 0, 0};
    #pragma unroll
    for (int i = 0; i < 8; ++i) {
        int n = n0 + (ty << 3) + i;
        if (n < N) {
            float ind = indS[(ty << 3) + i];
            float v0 = acc[i][0] + b3v[0] + ind * bbv[0];
            float v1 = acc[i][1] + b3v[1] + ind * bbv[1];
            float v2 = acc[i][2] + b3v[2] + ind * bbv[2];
            float v3 = acc[i][3] + b3v[3] + ind * bbv[3];
            *(float4*)(g_o1 + (size_t)n * 64 + (tx << 2)) = make_float4(v0, v1, v2, v3);
            cs[0] += v0; cs[1] += v1; cs[2] += v2; cs[3] += v3;
            cq[0] += v0 * v0; cq[1] += v1 * v1; cq[2] += v2 * v2; cq[3] += v3 * v3;
        }
    }
    #pragma unroll
    for (int j = 0; j < 4; ++j) {
        cs[j] += __shfl_xor_sync(0xffffffffu, cs[j], 16);
        cq[j] += __shfl_xor_sync(0xffffffffu, cq[j], 16);
    }
    if (lane < 16) {
        *(float4*)(wpart + w * 128 + (lane << 2))      = make_float4(cs[0], cs[1], cs[2], cs[3]);
        *(float4*)(wpart + w * 128 + 64 + (lane << 2)) = make_float4(cq[0], cq[1], cq[2], cq[3]);
    }
    __syncthreads();
    if (t < 128) {
        float s = 0.f;
        #pragma unroll
        for (int ww = 0; ww < 8; ++ww) s += wpart[ww * 128 + t];
        atomicAdd(&g_stats[128 + t], s);
    }
}

// ---------------- K6: out = relu(bn(o1)) @ w4 + b4 --------------------------
__global__ __launch_bounds__(256, 2)
void k_node2(const float* __restrict__ w4, const float* __restrict__ b4,
             float* __restrict__ out, int N)
{
    extern __shared__ float smem_f[];
    float* zT = smem_f;             // 64*128
    float* ws = zT + 64 * 128;      // 64*64
    int t = threadIdx.x;
    int w = t >> 5, lane = t & 31;
    int n0 = blockIdx.x * 128;

    {
        float4* wd = (float4*)ws;
        const float4* s4 = (const float4*)w4;
        for (int i = t; i < 64 * 16; i += 256) wd[i] = s4[i];
    }
    #pragma unroll
    for (int it = 0; it < 8; ++it) {
        int task = w + 8 * it;
        int k = ((task & 1) << 5) + lane;
        int ec = task >> 1;
        int n = n0 + 4 * ec;
        float a3 = g_bn[128 + k], c3 = g_bn[192 + k];
        float r0 = 0.f, r1 = 0.f, r2 = 0.f, r3 = 0.f;
        if (n + 0 < N) r0 = fmaxf(fmaf(g_o1[(size_t)(n + 0) * 64 + k], a3, c3), 0.f);
        if (n + 1 < N) r1 = fmaxf(fmaf(g_o1[(size_t)(n + 1) * 64 + k], a3, c3), 0.f);
        if (n + 2 < N) r2 = fmaxf(fmaf(g_o1[(size_t)(n + 2) * 64 + k], a3, c3), 0.f);
        if (n + 3 < N) r3 = fmaxf(fmaf(g_o1[(size_t)(n + 3) * 64 + k], a3, c3), 0.f);
        int es = (4 * ec) ^ ((k & 7) << 2);
        *(float4*)(zT + k * 128 + es) = make_float4(r0, r1, r2, r3);
    }
    __syncthreads();

    int tx = t & 15, ty = t >> 4;
    float acc[8][4];
    #pragma unroll
    for (int i = 0; i < 8; ++i)
        #pragma unroll
        for (int j = 0; j < 4; ++j) acc[i][j] = 0.f;

    gemm8x4<64>(zT, ws, tx, ty, acc);

    float bv0 = __ldg(b4 + 4 * tx + 0), bv1 = __ldg(b4 + 4 * tx + 1);
    float bv2 = __ldg(b4 + 4 * tx + 2), bv3 = __ldg(b4 + 4 * tx + 3);
    #pragma unroll
    for (int i = 0; i < 8; ++i) {
        int n = n0 + (ty << 3) + i;
        if (n < N) {
            *(float4*)(out + (size_t)n * 64 + (tx << 2)) =
                make_float4(acc[i][0] + bv0, acc[i][1] + bv1,
                            acc[i][2] + bv2, acc[i][3] + bv3);
        }
    }
}

// ---------------- host ------------------------------------------------------
extern "C" void kernel_launch(void* const* d_in, const int* in_sizes, int n_in,
                              void* d_out, int out_size)
{
    const float* x   = (const float*)d_in[0];
    const void*  ei  = d_in[1];
    const float* ea  = (const float*)d_in[2];
    const float* w1  = (const float*)d_in[5];
    const float* b1  = (const float*)d_in[6];
    const float* g1  = (const float*)d_in[7];
    const float* be1 = (const float*)d_in[8];
    const float* w2  = (const float*)d_in[9];
    const float* b2  = (const float*)d_in[10];
    const float* w3  = (const float*)d_in[11];
    const float* b3  = (const float*)d_in[12];
    const float* g3  = (const float*)d_in[13];
    const float* be3 = (const float*)d_in[14];
    const float* w4  = (const float*)d_in[15];
    const float* b4  = (const float*)d_in[16];
    int N = in_sizes[0] / 3;
    int E = in_sizes[2] / 64;

    const int SMEM_K1 = (67 * 128 + 67 * 64 + 1024) * 4;                  // 55552
    const int SMEM_K4 = (67 * 128 + 67 * 64 + 1024 + 256) * 4;            // 56576
    const int SMEM_K6 = (64 * 128 + 64 * 64) * 4;                         // 49152

    cudaFuncSetAttribute(k_edge,  cudaFuncAttributeMaxDynamicSharedMemorySize, SMEM_K1);
    cudaFuncSetAttribute(k_node1, cudaFuncAttributeMaxDynamicSharedMemorySize, SMEM_K4);
    cudaFuncSetAttribute(k_node2, cudaFuncAttributeMaxDynamicSharedMemorySize, SMEM_K6);

    void *p_spre, *p_cnt, *p_stats;
    cudaGetSymbolAddress(&p_spre,  g_spre);
    cudaGetSymbolAddress(&p_cnt,   g_cnt);
    cudaGetSymbolAddress(&p_stats, g_stats);
    cudaMemsetAsync(p_spre,  0, (size_t)N * 64 * sizeof(float), 0);
    cudaMemsetAsync(p_cnt,   0, (size_t)N * sizeof(float), 0);
    cudaMemsetAsync(p_stats, 0, 256 * sizeof(float), 0);

    k_detect<<<1, 1>>>((const int*)ei);
    k_prep<<<1, 256>>>(w2, w3, b2);
    k_edge<<<(E + 127) / 128, 256, SMEM_K1>>>(x, ei, ea, w1, b1, E);
    k_bnfin<<<1, 64>>>(g1, be1, 0, 0, 1.f / (float)E);
    k_scatter<<<(E + 31) / 32, 256>>>(ei, E);
    k_node1<<<(N + 127) / 128, 256, SMEM_K4>>>(x, w3, b3, N);
    k_bnfin<<<1, 64>>>(g3, be3, 128, 128, 1.f / (float)N);
    k_node2<<<(N + 127) / 128, 256, SMEM_K6>>>(w4, b4, (float*)d_out, N);
}